// round 2
// baseline (speedup 1.0000x reference)
#include <cuda_runtime.h>

#define NN 8192
#define NE 65536

// ---------------- zeroed scratch blob (single memset) -----------------------
// float offsets: deg(int) 0..8192, outcnt(int) 8192..16384,
// agg1 16384..409600, agg2 409600..671744, aggm 671744..802816, aggl 802816..933888
#define OFF_DEG    0
#define OFF_OUTCNT 8192
#define OFF_AGG1   16384
#define OFF_AGG2   409600
#define OFF_AGGM   671744
#define OFF_AGGL   802816
#define ZFLOATS    933888
__device__ __align__(16) float g_zbuf[ZFLOATS];

// ---------------- other scratch ---------------------------------------------
__device__ __align__(16) float g_T1[NN * 48 * 8];
__device__ __align__(16) float g_Tb1[NN * 48];
__device__ __align__(16) float g_T2[NN * 32 * 8];
__device__ __align__(16) float g_Tb2[NN * 32];
__device__ __align__(16) float g_h1[NN * 48];
__device__ __align__(16) float g_hm[NN * 16];
__device__ __align__(16) float g_hl[NN * 16];
__device__ float g_Wt1[64 * 432];
__device__ float g_Wt2[48 * 288];
__device__ int   g_off[NN];
__device__ int   g_cursor[NN];
__device__ int   g_perm[NE];
__device__ float g_dinv[NN];
__device__ float g_invdeg[NN];

__device__ __forceinline__ void red_add_v4(float* p, float a, float b, float c, float d) {
    asm volatile("red.global.add.v4.f32 [%0], {%1,%2,%3,%4};"
                 :: "l"(p), "f"(a), "f"(b), "f"(c), "f"(d) : "memory");
}

// ---------------- prep: degree counts + weight transposes -------------------
// Wt layout per layer: Wt[i*NC + c], c < 8*CO: o=c>>3, s=c&7 -> nn_w[s*(K*CO)+i*CO+o]
//                      c >= 8*CO:   o=c-8*CO -> nn_b[i*CO+o]
__global__ void prep_kernel(const int* __restrict__ ei,
                            const float* __restrict__ nn1w, const float* __restrict__ nn1b,
                            const float* __restrict__ nn2w, const float* __restrict__ nn2b,
                            int* __restrict__ outcnt, int* __restrict__ deg,
                            float* __restrict__ Wt1, float* __restrict__ Wt2) {
    int bx = blockIdx.x, t = threadIdx.x;
    if (bx < 256) {
        int e = bx * 256 + t;
        atomicAdd(&outcnt[ei[e]], 1);
        atomicAdd(&deg[ei[NE + e]], 1);
    } else if (bx < 364) {               // 27648 elems: K=64, CO=48, NC=432
        int idx = (bx - 256) * 256 + t;
        int i = idx / 432, c = idx - i * 432;
        float v;
        if (c < 384) { int o = c >> 3, s = c & 7; v = nn1w[s * 3072 + i * 48 + o]; }
        else         { int o = c - 384;           v = nn1b[i * 48 + o]; }
        Wt1[idx] = v;
    } else {                              // 13824 elems: K=48, CO=32, NC=288
        int idx = (bx - 364) * 256 + t;
        if (idx < 13824) {
            int i = idx / 288, c = idx - i * 288;
            float v;
            if (c < 256) { int o = c >> 3, s = c & 7; v = nn2w[s * 1536 + i * 32 + o]; }
            else         { int o = c - 256;           v = nn2b[i * 32 + o]; }
            Wt2[idx] = v;
        }
    }
}

// ---------------- block 0: exclusive scan of outcnt; blocks 1..8: dinv ------
__global__ void scan_dinv_kernel(const int* __restrict__ outcnt, const int* __restrict__ deg,
                                 int* __restrict__ off, int* __restrict__ cursor,
                                 float* __restrict__ dinv, float* __restrict__ invdeg) {
    int t = threadIdx.x;
    if (blockIdx.x == 0) {
        __shared__ int wsum[32];
        int base = t * 8;
        int v[8];
        int s = 0;
#pragma unroll
        for (int j = 0; j < 8; j++) { v[j] = outcnt[base + j]; s += v[j]; }
        int lane = t & 31, wid = t >> 5;
        int inc = s;
#pragma unroll
        for (int d = 1; d < 32; d <<= 1) {
            int n = __shfl_up_sync(0xFFFFFFFFu, inc, d);
            if (lane >= d) inc += n;
        }
        int excl_warp = inc - s;
        if (lane == 31) wsum[wid] = inc;
        __syncthreads();
        if (t < 32) {
            int w = wsum[t];
            int wi = w;
#pragma unroll
            for (int d = 1; d < 32; d <<= 1) {
                int n = __shfl_up_sync(0xFFFFFFFFu, wi, d);
                if (t >= d) wi += n;
            }
            wsum[t] = wi - w;   // exclusive warp offset
        }
        __syncthreads();
        int run = wsum[wid] + excl_warp;
#pragma unroll
        for (int j = 0; j < 8; j++) {
            off[base + j] = run;
            cursor[base + j] = run;
            run += v[j];
        }
    } else {
        int n = (blockIdx.x - 1) * 1024 + t;
        if (n < NN) {
            float d = (float)deg[n] + 1.0f;
            dinv[n] = rsqrtf(d);
            invdeg[n] = 1.0f / d;
        }
    }
}

// ---------------- scatter edges into src-sorted order -----------------------
__global__ void perm_kernel(const int* __restrict__ ei, int* __restrict__ cursor,
                            int* __restrict__ perm) {
    int e = blockIdx.x * 256 + threadIdx.x;
    int s = ei[e];
    int pos = atomicAdd(&cursor[s], 1);
    perm[pos] = e;
}

// ---------------- node GEMM: cols c<8CO -> T[n][c], else Tb[n][c-8CO] -------
template<int K, int CO>
__global__ void node_gemm_kernel(const float* __restrict__ X, const float* __restrict__ Wt,
                                 float* __restrict__ T, float* __restrict__ Tb) {
    constexpr int NC = CO * 9;
    __shared__ float xs[32][K];
    int n0 = blockIdx.y * 32;
    for (int idx = threadIdx.x; idx < 32 * K; idx += 256)
        xs[idx / K][idx % K] = X[n0 * K + idx];
    __syncthreads();

    int tx = threadIdx.x & 63;
    int ng = threadIdx.x >> 6;
    int c0 = blockIdx.x * 128 + tx;
    int c1 = c0 + 64;
    bool a0 = c0 < NC, a1 = c1 < NC;

    float acc0[8], acc1[8];
#pragma unroll
    for (int j = 0; j < 8; j++) { acc0[j] = 0.f; acc1[j] = 0.f; }

    const float* w0 = Wt + c0;
    const float* w1 = Wt + c1;
#pragma unroll 4
    for (int i = 0; i < K; i++) {
        float wv0 = a0 ? w0[i * NC] : 0.f;
        float wv1 = a1 ? w1[i * NC] : 0.f;
#pragma unroll
        for (int j = 0; j < 8; j++) {
            float xv = xs[ng * 8 + j][i];
            acc0[j] += xv * wv0;
            acc1[j] += xv * wv1;
        }
    }

    int nb = n0 + ng * 8;
    if (c0 < CO * 8) {
#pragma unroll
        for (int j = 0; j < 8; j++) T[(nb + j) * (CO * 8) + c0] = acc0[j];
    } else if (a0) {
        int o = c0 - CO * 8;
#pragma unroll
        for (int j = 0; j < 8; j++) Tb[(nb + j) * CO + o] = acc0[j];
    }
    if (c1 < CO * 8) {
#pragma unroll
        for (int j = 0; j < 8; j++) T[(nb + j) * (CO * 8) + c1] = acc1[j];
    } else if (a1) {
        int o = c1 - CO * 8;
#pragma unroll
        for (int j = 0; j < 8; j++) Tb[(nb + j) * CO + o] = acc1[j];
    }
}

// ---------------- edge NNConv over src-sorted edges, red.v4 scatter ---------
// CO=48: 192 threads, 16 edges (12 thr/edge); CO=32: 256 threads, 32 edges (8 thr/edge)
template<int CO, int EB, int TPE>
__global__ void edge_nnconv_kernel(const int* __restrict__ ei, const int* __restrict__ perm,
                                   const float* __restrict__ ea,
                                   const float* __restrict__ T, const float* __restrict__ Tb,
                                   float* __restrict__ agg) {
    __shared__ int s_eg[EB], s_src[EB], s_dst[EB];
    __shared__ __align__(16) float s_ea[EB * 8];
    int e0 = blockIdx.x * EB;
    int t = threadIdx.x;
    if (t < EB) {
        int eg = perm[e0 + t];
        s_eg[t] = eg;
        s_src[t] = ei[eg];
        s_dst[t] = ei[NE + eg];
    }
    __syncthreads();
    if (t < EB * 8) s_ea[t] = ea[s_eg[t >> 3] * 8 + (t & 7)];
    __syncthreads();

    int el = t / TPE;
    int o0 = (t - el * TPE) * 4;
    int src = s_src[el], dst = s_dst[el];
    const float4* eap = reinterpret_cast<const float4*>(&s_ea[el * 8]);
    float4 a0 = eap[0], a1 = eap[1];
    const float4* tp = reinterpret_cast<const float4*>(T + (src * CO + o0) * 8);
    float4 bb = *reinterpret_cast<const float4*>(Tb + src * CO + o0);
    float r[4];
    const float* bbf = reinterpret_cast<const float*>(&bb);
#pragma unroll
    for (int k = 0; k < 4; k++) {
        float4 t0 = tp[2 * k], t1 = tp[2 * k + 1];
        r[k] = bbf[k]
             + a0.x * t0.x + a0.y * t0.y + a0.z * t0.z + a0.w * t0.w
             + a1.x * t1.x + a1.y * t1.y + a1.z * t1.z + a1.w * t1.w;
    }
    red_add_v4(agg + dst * CO + o0, r[0], r[1], r[2], r[3]);
}

// ---------------- H = relu(agg + X @ root + bias) ---------------------------
template<int K, int CO>
__global__ void root_relu_kernel(const float* __restrict__ agg, const float* __restrict__ X,
                                 const float* __restrict__ root, const float* __restrict__ bias,
                                 float* __restrict__ H) {
    constexpr int NB = 16;
    constexpr int ITEMS = NB * CO / 256;
    __shared__ float xs[NB][K];
    int n0 = blockIdx.x * NB;
    for (int idx = threadIdx.x; idx < NB * K; idx += 256)
        xs[idx / K][idx % K] = X[n0 * K + idx];
    __syncthreads();
#pragma unroll
    for (int j = 0; j < ITEMS; j++) {
        int item = threadIdx.x + j * 256;
        int nl = item / CO, o = item - nl * CO;
        float acc = agg[(n0 + nl) * CO + o] + bias[o];
#pragma unroll 4
        for (int i = 0; i < K; i++) acc += xs[nl][i] * root[i * CO + o];
        H[(n0 + nl) * CO + o] = fmaxf(acc, 0.f);
    }
}

// ---------------- fused: h2 = relu(agg2 + h1@root2 + bias2); hm=h2@muw; hl=h2@lsw
__global__ void root2_heads_kernel(const float* __restrict__ agg, const float* __restrict__ H1,
                                   const float* __restrict__ root, const float* __restrict__ bias,
                                   const float* __restrict__ muw, const float* __restrict__ lsw,
                                   float* __restrict__ hm, float* __restrict__ hl) {
    __shared__ float xs[16][48];
    __shared__ float hs[16][32];
    int n0 = blockIdx.x * 16;
    for (int idx = threadIdx.x; idx < 16 * 48; idx += 256)
        xs[idx / 48][idx % 48] = H1[n0 * 48 + idx];
    __syncthreads();
#pragma unroll
    for (int j = 0; j < 2; j++) {
        int item = threadIdx.x + j * 256;
        int nl = item >> 5, o = item & 31;
        float acc = agg[(n0 + nl) * 32 + o] + bias[o];
#pragma unroll 4
        for (int i = 0; i < 48; i++) acc += xs[nl][i] * root[i * 32 + o];
        hs[nl][o] = fmaxf(acc, 0.f);
    }
    __syncthreads();
#pragma unroll
    for (int j = 0; j < 2; j++) {
        int item = threadIdx.x + j * 256;
        int nl = item >> 5;
        int r = item & 31;
        int head = r >> 4, o = r & 15;
        const float* W = head ? lsw : muw;
        float acc = 0.f;
#pragma unroll
        for (int i = 0; i < 32; i++) acc += hs[nl][i] * W[i * 16 + o];
        (head ? hl : hm)[(n0 + nl) * 16 + o] = acc;
    }
}

// ---------------- GCN edge scatter (src-sorted, red.v4) ---------------------
__global__ void gcn_edge_kernel(const int* __restrict__ ei, const int* __restrict__ perm,
                                const float* __restrict__ hm, const float* __restrict__ hl,
                                const float* __restrict__ dinv,
                                float* __restrict__ aggm, float* __restrict__ aggl) {
    __shared__ int s_src[32], s_dst[32];
    __shared__ float s_w[32];
    int e0 = blockIdx.x * 32;
    int t = threadIdx.x;
    if (t < 32) {
        int eg = perm[e0 + t];
        int s = ei[eg], d = ei[NE + eg];
        s_src[t] = s;
        s_dst[t] = d;
        s_w[t] = dinv[s] * dinv[d];
    }
    __syncthreads();
    int el = t >> 3, r = t & 7;
    int head = r >> 2, q = r & 3;
    int src = s_src[el], dst = s_dst[el];
    float w = s_w[el];
    const float* h = head ? hl : hm;
    float4 v = *reinterpret_cast<const float4*>(h + src * 16 + q * 4);
    float* a = head ? aggl : aggm;
    red_add_v4(a + dst * 16 + q * 4, v.x * w, v.y * w, v.z * w, v.w * w);
}

// ---------------- final: out = agg + h*invdeg + bias (mu then ls) -----------
__global__ void out_kernel(const float* __restrict__ aggm, const float* __restrict__ aggl,
                           const float* __restrict__ hm, const float* __restrict__ hl,
                           const float* __restrict__ invdeg, const float* __restrict__ mub,
                           const float* __restrict__ lsb, float* __restrict__ out) {
    int i4 = blockIdx.x * 256 + threadIdx.x;   // < 32768 float4 items per head
    int n = i4 >> 2, q = i4 & 3;
    float iv = invdeg[n];
    float4* out4 = reinterpret_cast<float4*>(out);
    float4 am = reinterpret_cast<const float4*>(aggm)[i4];
    float4 vm = reinterpret_cast<const float4*>(hm)[i4];
    float4 bm = reinterpret_cast<const float4*>(mub)[q];
    out4[i4] = make_float4(am.x + vm.x * iv + bm.x, am.y + vm.y * iv + bm.y,
                           am.z + vm.z * iv + bm.z, am.w + vm.w * iv + bm.w);
    float4 al = reinterpret_cast<const float4*>(aggl)[i4];
    float4 vl = reinterpret_cast<const float4*>(hl)[i4];
    float4 bl = reinterpret_cast<const float4*>(lsb)[q];
    out4[32768 + i4] = make_float4(al.x + vl.x * iv + bl.x, al.y + vl.y * iv + bl.y,
                                   al.z + vl.z * iv + bl.z, al.w + vl.w * iv + bl.w);
}

// ---------------- launcher --------------------------------------------------
extern "C" void kernel_launch(void* const* d_in, const int* in_sizes, int n_in,
                              void* d_out, int out_size) {
    const float* x      = (const float*)d_in[0];
    const int*   ei     = (const int*)  d_in[1];
    const float* ea     = (const float*)d_in[2];
    const float* nn1_w  = (const float*)d_in[3];
    const float* nn1_b  = (const float*)d_in[4];
    const float* root1  = (const float*)d_in[5];
    const float* bias1  = (const float*)d_in[6];
    const float* nn2_w  = (const float*)d_in[7];
    const float* nn2_b  = (const float*)d_in[8];
    const float* root2  = (const float*)d_in[9];
    const float* bias2  = (const float*)d_in[10];
    const float* mu_w   = (const float*)d_in[11];
    const float* mu_b   = (const float*)d_in[12];
    const float* ls_w   = (const float*)d_in[13];
    const float* ls_b   = (const float*)d_in[14];
    float* out = (float*)d_out;

    void *pz, *pT1, *pTb1, *pT2, *pTb2, *ph1, *phm, *phl;
    void *pWt1, *pWt2, *poff, *pcur, *pperm, *pdinv, *pinvdeg;
    cudaGetSymbolAddress(&pz, g_zbuf);
    cudaGetSymbolAddress(&pT1, g_T1);
    cudaGetSymbolAddress(&pTb1, g_Tb1);
    cudaGetSymbolAddress(&pT2, g_T2);
    cudaGetSymbolAddress(&pTb2, g_Tb2);
    cudaGetSymbolAddress(&ph1, g_h1);
    cudaGetSymbolAddress(&phm, g_hm);
    cudaGetSymbolAddress(&phl, g_hl);
    cudaGetSymbolAddress(&pWt1, g_Wt1);
    cudaGetSymbolAddress(&pWt2, g_Wt2);
    cudaGetSymbolAddress(&poff, g_off);
    cudaGetSymbolAddress(&pcur, g_cursor);
    cudaGetSymbolAddress(&pperm, g_perm);
    cudaGetSymbolAddress(&pdinv, g_dinv);
    cudaGetSymbolAddress(&pinvdeg, g_invdeg);

    float* zb = (float*)pz;
    int*   deg    = (int*)(zb + OFF_DEG);
    int*   outcnt = (int*)(zb + OFF_OUTCNT);
    float* agg1   = zb + OFF_AGG1;
    float* agg2   = zb + OFF_AGG2;
    float* aggm   = zb + OFF_AGGM;
    float* aggl   = zb + OFF_AGGL;

    cudaMemsetAsync(pz, 0, ZFLOATS * sizeof(float), 0);

    prep_kernel<<<418, 256>>>(ei, nn1_w, nn1_b, nn2_w, nn2_b,
                              outcnt, deg, (float*)pWt1, (float*)pWt2);
    scan_dinv_kernel<<<9, 1024>>>(outcnt, deg, (int*)poff, (int*)pcur,
                                  (float*)pdinv, (float*)pinvdeg);
    perm_kernel<<<256, 256>>>(ei, (int*)pcur, (int*)pperm);

    // layer 1
    node_gemm_kernel<64, 48><<<dim3(4, 256), 256>>>(x, (float*)pWt1, (float*)pT1, (float*)pTb1);
    edge_nnconv_kernel<48, 16, 12><<<NE / 16, 192>>>(ei, (int*)pperm, ea,
                                                     (float*)pT1, (float*)pTb1, agg1);
    root_relu_kernel<64, 48><<<NN / 16, 256>>>(agg1, x, root1, bias1, (float*)ph1);

    // layer 2
    node_gemm_kernel<48, 32><<<dim3(3, 256), 256>>>((float*)ph1, (float*)pWt2,
                                                    (float*)pT2, (float*)pTb2);
    edge_nnconv_kernel<32, 32, 8><<<NE / 32, 256>>>(ei, (int*)pperm, ea,
                                                    (float*)pT2, (float*)pTb2, agg2);
    root2_heads_kernel<<<NN / 16, 256>>>(agg2, (float*)ph1, root2, bias2,
                                         mu_w, ls_w, (float*)phm, (float*)phl);

    // GCN scatter + output
    gcn_edge_kernel<<<NE / 32, 256>>>(ei, (int*)pperm, (float*)phm, (float*)phl,
                                      (float*)pdinv, aggm, aggl);
    out_kernel<<<128, 256>>>(aggm, aggl, (float*)phm, (float*)phl,
                             (float*)pinvdeg, mu_b, ls_b, out);
}

// round 3
// speedup vs baseline: 1.3529x; 1.3529x over previous
#include <cuda_runtime.h>

#define NN 8192
#define NE 65536

typedef unsigned long long ull;

// ---------------- zeroed scratch blob (single memset) -----------------------
#define OFF_DEG    0
#define OFF_AGG1   8192
#define OFF_AGG2   401408
#define OFF_AGGM   663552
#define OFF_AGGL   794624
#define ZFLOATS    925696
__device__ __align__(16) float g_zbuf[ZFLOATS];

// ---------------- other scratch ---------------------------------------------
__device__ __align__(16) float g_T1[NN * 48 * 8];
__device__ __align__(16) float g_Tb1[NN * 48];
__device__ __align__(16) float g_T2[NN * 32 * 8];
__device__ __align__(16) float g_Tb2[NN * 32];
__device__ __align__(16) float g_h1[NN * 48];
__device__ __align__(16) float g_hm[NN * 16];
__device__ __align__(16) float g_hl[NN * 16];
__device__ float g_Wt1[64 * 432];
__device__ float g_Wt2[48 * 288];
__device__ float g_dinv[NN];
__device__ float g_invdeg[NN];

// ---------------- packed fp32x2 helpers (Blackwell FFMA2) -------------------
__device__ __forceinline__ ull pack2(float a, float b) {
    ull r;
    asm("mov.b64 %0, {%1, %2};" : "=l"(r) : "f"(a), "f"(b));
    return r;
}
__device__ __forceinline__ void fma2(ull& d, ull a, ull b) {
    asm("fma.rn.f32x2 %0, %1, %2, %0;" : "+l"(d) : "l"(a), "l"(b));
}
__device__ __forceinline__ float2 unpack2(ull v) {
    float lo, hi;
    asm("mov.b64 {%0, %1}, %2;" : "=f"(lo), "=f"(hi) : "l"(v));
    return make_float2(lo, hi);
}

__device__ __forceinline__ void red_add_v4(float* p, float a, float b, float c, float d) {
    asm volatile("red.global.add.v4.f32 [%0], {%1,%2,%3,%4};"
                 :: "l"(p), "f"(a), "f"(b), "f"(c), "f"(d) : "memory");
}

// ---------------- prep: degree counts + weight transposes -------------------
// Wt layout: Wt[i*NC + c]; c<8*CO: o=c>>3,s=c&7 -> nn_w[s*(K*CO)+i*CO+o]; else bias col.
__global__ void prep_kernel(const int* __restrict__ ei,
                            const float* __restrict__ nn1w, const float* __restrict__ nn1b,
                            const float* __restrict__ nn2w, const float* __restrict__ nn2b,
                            int* __restrict__ deg,
                            float* __restrict__ Wt1, float* __restrict__ Wt2) {
    int bx = blockIdx.x, t = threadIdx.x;
    if (bx < 256) {
        int e = bx * 256 + t;
        atomicAdd(&deg[ei[NE + e]], 1);
    } else if (bx < 364) {               // 27648: K=64, CO=48, NC=432
        int idx = (bx - 256) * 256 + t;
        int i = idx / 432, c = idx - i * 432;
        float v;
        if (c < 384) { int o = c >> 3, s = c & 7; v = nn1w[s * 3072 + i * 48 + o]; }
        else         { int o = c - 384;           v = nn1b[i * 48 + o]; }
        Wt1[idx] = v;
    } else {                              // 13824: K=48, CO=32, NC=288
        int idx = (bx - 364) * 256 + t;
        if (idx < 13824) {
            int i = idx / 288, c = idx - i * 288;
            float v;
            if (c < 256) { int o = c >> 3, s = c & 7; v = nn2w[s * 1536 + i * 32 + o]; }
            else         { int o = c - 256;           v = nn2b[i * 32 + o]; }
            Wt2[idx] = v;
        }
    }
}

__global__ void dinv_kernel(const int* __restrict__ deg, float* __restrict__ dinv,
                            float* __restrict__ invdeg) {
    int n = blockIdx.x * 1024 + threadIdx.x;
    float d = (float)deg[n] + 1.0f;
    dinv[n] = rsqrtf(d);
    invdeg[n] = 1.0f / d;
}

// ---------------- node GEMM via FFMA2: 64 nodes x 128 cols per block --------
// thread = 8 nodes x 4 cols; warp wd owns nodes wd*8..+7 (x via broadcast LDS).
template<int K, int CO>
__global__ void __launch_bounds__(256) node_gemm_kernel(
        const float* __restrict__ X, const float* __restrict__ Wt,
        float* __restrict__ T, float* __restrict__ Tb) {
    constexpr int NC = CO * 9;
    __shared__ float xs[64 * K];
    __shared__ float ws[K * 128];
    int tid = threadIdx.x;
    int n0 = blockIdx.y * 64;
    int cbase = blockIdx.x * 128;

    const float4* X4 = reinterpret_cast<const float4*>(X + n0 * K);
    float4* xs4 = reinterpret_cast<float4*>(xs);
#pragma unroll
    for (int idx = tid; idx < 64 * K / 4; idx += 256) xs4[idx] = X4[idx];
    for (int idx = tid; idx < K * 128; idx += 256) {
        int i = idx >> 7, c = idx & 127;
        int cc = cbase + c;
        ws[idx] = (cc < NC) ? Wt[i * NC + cc] : 0.f;
    }
    __syncthreads();

    int lane = tid & 31, wd = tid >> 5;
    int cl = lane * 4;
    ull acc[16];
#pragma unroll
    for (int j = 0; j < 16; j++) acc[j] = 0ull;

    const float* xrow = xs + (wd * 8) * K;
#pragma unroll 4
    for (int i = 0; i < K; i++) {
        ull xp[4];
#pragma unroll
        for (int p = 0; p < 4; p++)
            xp[p] = pack2(xrow[(2 * p) * K + i], xrow[(2 * p + 1) * K + i]);
        float4 wv = *reinterpret_cast<const float4*>(ws + i * 128 + cl);
        ull w2[4] = { pack2(wv.x, wv.x), pack2(wv.y, wv.y),
                      pack2(wv.z, wv.z), pack2(wv.w, wv.w) };
#pragma unroll
        for (int p = 0; p < 4; p++)
#pragma unroll
            for (int q = 0; q < 4; q++)
                fma2(acc[p * 4 + q], xp[p], w2[q]);
    }

    int c0 = cbase + cl;
#pragma unroll
    for (int p = 0; p < 4; p++) {
        float2 v0 = unpack2(acc[p * 4 + 0]);
        float2 v1 = unpack2(acc[p * 4 + 1]);
        float2 v2 = unpack2(acc[p * 4 + 2]);
        float2 v3 = unpack2(acc[p * 4 + 3]);
        int na = n0 + wd * 8 + 2 * p;
        float4 ra = make_float4(v0.x, v1.x, v2.x, v3.x);
        float4 rb = make_float4(v0.y, v1.y, v2.y, v3.y);
        if (c0 < CO * 8) {
            *reinterpret_cast<float4*>(T + na * (CO * 8) + c0) = ra;
            *reinterpret_cast<float4*>(T + (na + 1) * (CO * 8) + c0) = rb;
        } else if (c0 < NC) {
            *reinterpret_cast<float4*>(Tb + na * CO + (c0 - CO * 8)) = ra;
            *reinterpret_cast<float4*>(Tb + (na + 1) * CO + (c0 - CO * 8)) = rb;
        }
    }
}

// ---------------- edge NNConv (natural order, red.v4) -----------------------
// thread handles 4 outputs of one edge: 8x LDG.128 (T row) + 1 LDG.128 (bias) + red.v4
template<int CO, int EB, int TPE>
__global__ void edge_nnconv_kernel(const int* __restrict__ ei, const float* __restrict__ ea,
                                   const float* __restrict__ T, const float* __restrict__ Tb,
                                   float* __restrict__ agg) {
    __shared__ int s_src[EB], s_dst[EB];
    __shared__ __align__(16) float s_ea[EB * 8];
    int e0 = blockIdx.x * EB;
    int t = threadIdx.x;
    if (t < EB) {
        s_src[t] = ei[e0 + t];
        s_dst[t] = ei[NE + e0 + t];
    }
    if (t < EB * 2)
        reinterpret_cast<float4*>(s_ea)[t] =
            reinterpret_cast<const float4*>(ea + e0 * 8)[t];
    __syncthreads();

    int el = t / TPE;
    int o0 = (t - el * TPE) * 4;
    int src = s_src[el], dst = s_dst[el];
    const float4* eap = reinterpret_cast<const float4*>(&s_ea[el * 8]);
    float4 a0 = eap[0], a1 = eap[1];
    const float4* tp = reinterpret_cast<const float4*>(T + (src * CO + o0) * 8);
    float4 bb = *reinterpret_cast<const float4*>(Tb + src * CO + o0);
    float r[4];
    const float* bbf = reinterpret_cast<const float*>(&bb);
#pragma unroll
    for (int k = 0; k < 4; k++) {
        float4 t0 = tp[2 * k], t1 = tp[2 * k + 1];
        r[k] = bbf[k]
             + a0.x * t0.x + a0.y * t0.y + a0.z * t0.z + a0.w * t0.w
             + a1.x * t1.x + a1.y * t1.y + a1.z * t1.z + a1.w * t1.w;
    }
    red_add_v4(agg + dst * CO + o0, r[0], r[1], r[2], r[3]);
}

// ---------------- H = relu(agg + X @ root + bias) ---------------------------
template<int K, int CO>
__global__ void root_relu_kernel(const float* __restrict__ agg, const float* __restrict__ X,
                                 const float* __restrict__ root, const float* __restrict__ bias,
                                 float* __restrict__ H) {
    constexpr int NB = 16;
    constexpr int ITEMS = NB * CO / 256;
    __shared__ float xs[NB][K];
    int n0 = blockIdx.x * NB;
    for (int idx = threadIdx.x; idx < NB * K; idx += 256)
        xs[idx / K][idx % K] = X[n0 * K + idx];
    __syncthreads();
#pragma unroll
    for (int j = 0; j < ITEMS; j++) {
        int item = threadIdx.x + j * 256;
        int nl = item / CO, o = item - nl * CO;
        float acc = agg[(n0 + nl) * CO + o] + bias[o];
#pragma unroll 4
        for (int i = 0; i < K; i++) acc += xs[nl][i] * root[i * CO + o];
        H[(n0 + nl) * CO + o] = fmaxf(acc, 0.f);
    }
}

// ---------------- fused: h2 = relu(...); hm = h2@muw; hl = h2@lsw -----------
__global__ void root2_heads_kernel(const float* __restrict__ agg, const float* __restrict__ H1,
                                   const float* __restrict__ root, const float* __restrict__ bias,
                                   const float* __restrict__ muw, const float* __restrict__ lsw,
                                   float* __restrict__ hm, float* __restrict__ hl) {
    __shared__ float xs[16][48];
    __shared__ float hs[16][32];
    int n0 = blockIdx.x * 16;
    for (int idx = threadIdx.x; idx < 16 * 48; idx += 256)
        xs[idx / 48][idx % 48] = H1[n0 * 48 + idx];
    __syncthreads();
#pragma unroll
    for (int j = 0; j < 2; j++) {
        int item = threadIdx.x + j * 256;
        int nl = item >> 5, o = item & 31;
        float acc = agg[(n0 + nl) * 32 + o] + bias[o];
#pragma unroll 4
        for (int i = 0; i < 48; i++) acc += xs[nl][i] * root[i * 32 + o];
        hs[nl][o] = fmaxf(acc, 0.f);
    }
    __syncthreads();
#pragma unroll
    for (int j = 0; j < 2; j++) {
        int item = threadIdx.x + j * 256;
        int nl = item >> 5;
        int r = item & 31;
        int head = r >> 4, o = r & 15;
        const float* W = head ? lsw : muw;
        float acc = 0.f;
#pragma unroll
        for (int i = 0; i < 32; i++) acc += hs[nl][i] * W[i * 16 + o];
        (head ? hl : hm)[(n0 + nl) * 16 + o] = acc;
    }
}

// ---------------- GCN edge scatter (natural order, red.v4) ------------------
__global__ void gcn_edge_kernel(const int* __restrict__ ei,
                                const float* __restrict__ hm, const float* __restrict__ hl,
                                const float* __restrict__ dinv,
                                float* __restrict__ aggm, float* __restrict__ aggl) {
    __shared__ int s_src[32], s_dst[32];
    __shared__ float s_w[32];
    int e0 = blockIdx.x * 32;
    int t = threadIdx.x;
    if (t < 32) {
        int s = ei[e0 + t], d = ei[NE + e0 + t];
        s_src[t] = s;
        s_dst[t] = d;
        s_w[t] = dinv[s] * dinv[d];
    }
    __syncthreads();
    int el = t >> 3, r = t & 7;
    int head = r >> 2, q = r & 3;
    int src = s_src[el], dst = s_dst[el];
    float w = s_w[el];
    const float* h = head ? hl : hm;
    float4 v = *reinterpret_cast<const float4*>(h + src * 16 + q * 4);
    float* a = head ? aggl : aggm;
    red_add_v4(a + dst * 16 + q * 4, v.x * w, v.y * w, v.z * w, v.w * w);
}

// ---------------- final: out = agg + h*invdeg + bias (mu then ls) -----------
__global__ void out_kernel(const float* __restrict__ aggm, const float* __restrict__ aggl,
                           const float* __restrict__ hm, const float* __restrict__ hl,
                           const float* __restrict__ invdeg, const float* __restrict__ mub,
                           const float* __restrict__ lsb, float* __restrict__ out) {
    int i4 = blockIdx.x * 256 + threadIdx.x;
    int n = i4 >> 2, q = i4 & 3;
    float iv = invdeg[n];
    float4* out4 = reinterpret_cast<float4*>(out);
    float4 am = reinterpret_cast<const float4*>(aggm)[i4];
    float4 vm = reinterpret_cast<const float4*>(hm)[i4];
    float4 bm = reinterpret_cast<const float4*>(mub)[q];
    out4[i4] = make_float4(am.x + vm.x * iv + bm.x, am.y + vm.y * iv + bm.y,
                           am.z + vm.z * iv + bm.z, am.w + vm.w * iv + bm.w);
    float4 al = reinterpret_cast<const float4*>(aggl)[i4];
    float4 vl = reinterpret_cast<const float4*>(hl)[i4];
    float4 bl = reinterpret_cast<const float4*>(lsb)[q];
    out4[32768 + i4] = make_float4(al.x + vl.x * iv + bl.x, al.y + vl.y * iv + bl.y,
                                   al.z + vl.z * iv + bl.z, al.w + vl.w * iv + bl.w);
}

// ---------------- launcher --------------------------------------------------
extern "C" void kernel_launch(void* const* d_in, const int* in_sizes, int n_in,
                              void* d_out, int out_size) {
    const float* x      = (const float*)d_in[0];
    const int*   ei     = (const int*)  d_in[1];
    const float* ea     = (const float*)d_in[2];
    const float* nn1_w  = (const float*)d_in[3];
    const float* nn1_b  = (const float*)d_in[4];
    const float* root1  = (const float*)d_in[5];
    const float* bias1  = (const float*)d_in[6];
    const float* nn2_w  = (const float*)d_in[7];
    const float* nn2_b  = (const float*)d_in[8];
    const float* root2  = (const float*)d_in[9];
    const float* bias2  = (const float*)d_in[10];
    const float* mu_w   = (const float*)d_in[11];
    const float* mu_b   = (const float*)d_in[12];
    const float* ls_w   = (const float*)d_in[13];
    const float* ls_b   = (const float*)d_in[14];
    float* out = (float*)d_out;

    void *pz, *pT1, *pTb1, *pT2, *pTb2, *ph1, *phm, *phl;
    void *pWt1, *pWt2, *pdinv, *pinvdeg;
    cudaGetSymbolAddress(&pz, g_zbuf);
    cudaGetSymbolAddress(&pT1, g_T1);
    cudaGetSymbolAddress(&pTb1, g_Tb1);
    cudaGetSymbolAddress(&pT2, g_T2);
    cudaGetSymbolAddress(&pTb2, g_Tb2);
    cudaGetSymbolAddress(&ph1, g_h1);
    cudaGetSymbolAddress(&phm, g_hm);
    cudaGetSymbolAddress(&phl, g_hl);
    cudaGetSymbolAddress(&pWt1, g_Wt1);
    cudaGetSymbolAddress(&pWt2, g_Wt2);
    cudaGetSymbolAddress(&pdinv, g_dinv);
    cudaGetSymbolAddress(&pinvdeg, g_invdeg);

    float* zb = (float*)pz;
    int*   deg  = (int*)(zb + OFF_DEG);
    float* agg1 = zb + OFF_AGG1;
    float* agg2 = zb + OFF_AGG2;
    float* aggm = zb + OFF_AGGM;
    float* aggl = zb + OFF_AGGL;

    cudaMemsetAsync(pz, 0, ZFLOATS * sizeof(float), 0);

    prep_kernel<<<418, 256>>>(ei, nn1_w, nn1_b, nn2_w, nn2_b,
                              deg, (float*)pWt1, (float*)pWt2);
    dinv_kernel<<<8, 1024>>>(deg, (float*)pdinv, (float*)pinvdeg);

    // layer 1
    node_gemm_kernel<64, 48><<<dim3(4, 128), 256>>>(x, (float*)pWt1, (float*)pT1, (float*)pTb1);
    edge_nnconv_kernel<48, 32, 12><<<NE / 32, 384>>>(ei, ea, (float*)pT1, (float*)pTb1, agg1);
    root_relu_kernel<64, 48><<<NN / 16, 256>>>(agg1, x, root1, bias1, (float*)ph1);

    // layer 2
    node_gemm_kernel<48, 32><<<dim3(3, 128), 256>>>((float*)ph1, (float*)pWt2,
                                                    (float*)pT2, (float*)pTb2);
    edge_nnconv_kernel<32, 32, 8><<<NE / 32, 256>>>(ei, ea, (float*)pT2, (float*)pTb2, agg2);
    root2_heads_kernel<<<NN / 16, 256>>>(agg2, (float*)ph1, root2, bias2,
                                         mu_w, ls_w, (float*)phm, (float*)phl);

    // GCN scatter + output
    gcn_edge_kernel<<<NE / 32, 256>>>(ei, (float*)phm, (float*)phl,
                                      (float*)pdinv, aggm, aggl);
    out_kernel<<<128, 256>>>(aggm, aggl, (float*)phm, (float*)phl,
                             (float*)pinvdeg, mu_b, ls_b, out);
}

// round 4
// speedup vs baseline: 1.5227x; 1.1255x over previous
#include <cuda_runtime.h>

#define NN 8192
#define NE 65536

typedef unsigned long long ull;

// ---------------- zeroed scratch blob (single memset) -----------------------
#define OFF_DEG    0
#define OFF_OUTCNT 8192
#define OFF_AGG1   16384
#define OFF_AGG2   409600
#define OFF_AGGM   671744
#define OFF_AGGL   802816
#define ZFLOATS    933888
__device__ __align__(16) float g_zbuf[ZFLOATS];

// ---------------- other scratch ---------------------------------------------
__device__ __align__(16) float g_T1[NN * 48 * 8];
__device__ __align__(16) float g_Tb1[NN * 48];
__device__ __align__(16) float g_T2[NN * 32 * 8];
__device__ __align__(16) float g_Tb2[NN * 32];
__device__ __align__(16) float g_h1[NN * 48];
__device__ __align__(16) float g_hm[NN * 16];
__device__ __align__(16) float g_hl[NN * 16];
__device__ __align__(16) float g_sea[NE * 8];   // edge_attr in src-sorted order
__device__ int   g_sdst[NE];                    // dst in src-sorted order
__device__ int   g_off[NN + 1];                 // CSR offsets by src
__device__ int   g_cursor[NN];
__device__ float g_Wt1[64 * 432];
__device__ float g_Wt2[48 * 288];
__device__ float g_dinv[NN];
__device__ float g_invdeg[NN];

// ---------------- packed fp32x2 helpers (Blackwell FFMA2) -------------------
__device__ __forceinline__ ull pack2(float a, float b) {
    ull r;
    asm("mov.b64 %0, {%1, %2};" : "=l"(r) : "f"(a), "f"(b));
    return r;
}
__device__ __forceinline__ void fma2(ull& d, ull a, ull b) {
    asm("fma.rn.f32x2 %0, %1, %2, %0;" : "+l"(d) : "l"(a), "l"(b));
}
__device__ __forceinline__ float2 unpack2(ull v) {
    float lo, hi;
    asm("mov.b64 {%0, %1}, %2;" : "=f"(lo), "=f"(hi) : "l"(v));
    return make_float2(lo, hi);
}

__device__ __forceinline__ void red_add_v4(float* p, float a, float b, float c, float d) {
    asm volatile("red.global.add.v4.f32 [%0], {%1,%2,%3,%4};"
                 :: "l"(p), "f"(a), "f"(b), "f"(c), "f"(d) : "memory");
}

// ---------------- prep: degree/outdeg counts + weight transposes ------------
__global__ void prep_kernel(const int* __restrict__ ei,
                            const float* __restrict__ nn1w, const float* __restrict__ nn1b,
                            const float* __restrict__ nn2w, const float* __restrict__ nn2b,
                            int* __restrict__ outcnt, int* __restrict__ deg,
                            float* __restrict__ Wt1, float* __restrict__ Wt2) {
    int bx = blockIdx.x, t = threadIdx.x;
    if (bx < 256) {
        int e = bx * 256 + t;
        atomicAdd(&outcnt[ei[e]], 1);
        atomicAdd(&deg[ei[NE + e]], 1);
    } else if (bx < 364) {               // 27648: K=64, CO=48, NC=432
        int idx = (bx - 256) * 256 + t;
        int i = idx / 432, c = idx - i * 432;
        float v;
        if (c < 384) { int o = c >> 3, s = c & 7; v = nn1w[s * 3072 + i * 48 + o]; }
        else         { int o = c - 384;           v = nn1b[i * 48 + o]; }
        Wt1[idx] = v;
    } else {                              // 13824: K=48, CO=32, NC=288
        int idx = (bx - 364) * 256 + t;
        if (idx < 13824) {
            int i = idx / 288, c = idx - i * 288;
            float v;
            if (c < 256) { int o = c >> 3, s = c & 7; v = nn2w[s * 1536 + i * 32 + o]; }
            else         { int o = c - 256;           v = nn2b[i * 32 + o]; }
            Wt2[idx] = v;
        }
    }
}

// ---------------- block 0: exclusive scan of outcnt; blocks 1..8: dinv ------
__global__ void scan_dinv_kernel(const int* __restrict__ outcnt, const int* __restrict__ deg,
                                 int* __restrict__ off, int* __restrict__ cursor,
                                 float* __restrict__ dinv, float* __restrict__ invdeg) {
    int t = threadIdx.x;
    if (blockIdx.x == 0) {
        __shared__ int wsum[32];
        int base = t * 8;
        int v[8];
        int s = 0;
#pragma unroll
        for (int j = 0; j < 8; j++) { v[j] = outcnt[base + j]; s += v[j]; }
        int lane = t & 31, wid = t >> 5;
        int inc = s;
#pragma unroll
        for (int d = 1; d < 32; d <<= 1) {
            int n = __shfl_up_sync(0xFFFFFFFFu, inc, d);
            if (lane >= d) inc += n;
        }
        int excl_warp = inc - s;
        if (lane == 31) wsum[wid] = inc;
        __syncthreads();
        if (t < 32) {
            int w = wsum[t];
            int wi = w;
#pragma unroll
            for (int d = 1; d < 32; d <<= 1) {
                int n = __shfl_up_sync(0xFFFFFFFFu, wi, d);
                if (t >= d) wi += n;
            }
            wsum[t] = wi - w;
        }
        __syncthreads();
        int run = wsum[wid] + excl_warp;
#pragma unroll
        for (int j = 0; j < 8; j++) {
            off[base + j] = run;
            cursor[base + j] = run;
            run += v[j];
        }
        if (t == 1023) off[NN] = NE;
    } else {
        int n = (blockIdx.x - 1) * 1024 + t;
        float d = (float)deg[n] + 1.0f;
        dinv[n] = rsqrtf(d);
        invdeg[n] = 1.0f / d;
    }
}

// ---------------- scatter edge payloads into src-sorted order ---------------
__global__ void perm_kernel(const int* __restrict__ ei, const float* __restrict__ ea,
                            int* __restrict__ cursor,
                            int* __restrict__ sdst, float* __restrict__ sea) {
    int e = blockIdx.x * 256 + threadIdx.x;
    int s = ei[e];
    int pos = atomicAdd(&cursor[s], 1);
    sdst[pos] = ei[NE + e];
    const float4* ev = reinterpret_cast<const float4*>(ea + e * 8);
    float4* sv = reinterpret_cast<float4*>(sea + pos * 8);
    sv[0] = ev[0];
    sv[1] = ev[1];
}

// ---------------- node GEMM via FFMA2: 64 nodes x 128 cols per block --------
template<int K, int CO>
__global__ void __launch_bounds__(256) node_gemm_kernel(
        const float* __restrict__ X, const float* __restrict__ Wt,
        float* __restrict__ T, float* __restrict__ Tb) {
    constexpr int NC = CO * 9;
    __shared__ float xs[64 * K];
    __shared__ float ws[K * 128];
    int tid = threadIdx.x;
    int n0 = blockIdx.y * 64;
    int cbase = blockIdx.x * 128;

    const float4* X4 = reinterpret_cast<const float4*>(X + n0 * K);
    float4* xs4 = reinterpret_cast<float4*>(xs);
#pragma unroll
    for (int idx = tid; idx < 64 * K / 4; idx += 256) xs4[idx] = X4[idx];
    for (int idx = tid; idx < K * 128; idx += 256) {
        int i = idx >> 7, c = idx & 127;
        int cc = cbase + c;
        ws[idx] = (cc < NC) ? Wt[i * NC + cc] : 0.f;
    }
    __syncthreads();

    int lane = tid & 31, wd = tid >> 5;
    int cl = lane * 4;
    ull acc[16];
#pragma unroll
    for (int j = 0; j < 16; j++) acc[j] = 0ull;

    const float* xrow = xs + (wd * 8) * K;
#pragma unroll 4
    for (int i = 0; i < K; i++) {
        ull xp[4];
#pragma unroll
        for (int p = 0; p < 4; p++)
            xp[p] = pack2(xrow[(2 * p) * K + i], xrow[(2 * p + 1) * K + i]);
        float4 wv = *reinterpret_cast<const float4*>(ws + i * 128 + cl);
        ull w2[4] = { pack2(wv.x, wv.x), pack2(wv.y, wv.y),
                      pack2(wv.z, wv.z), pack2(wv.w, wv.w) };
#pragma unroll
        for (int p = 0; p < 4; p++)
#pragma unroll
            for (int q = 0; q < 4; q++)
                fma2(acc[p * 4 + q], xp[p], w2[q]);
    }

    int c0 = cbase + cl;
#pragma unroll
    for (int p = 0; p < 4; p++) {
        float2 v0 = unpack2(acc[p * 4 + 0]);
        float2 v1 = unpack2(acc[p * 4 + 1]);
        float2 v2 = unpack2(acc[p * 4 + 2]);
        float2 v3 = unpack2(acc[p * 4 + 3]);
        int na = n0 + wd * 8 + 2 * p;
        float4 ra = make_float4(v0.x, v1.x, v2.x, v3.x);
        float4 rb = make_float4(v0.y, v1.y, v2.y, v3.y);
        if (c0 < CO * 8) {
            *reinterpret_cast<float4*>(T + na * (CO * 8) + c0) = ra;
            *reinterpret_cast<float4*>(T + (na + 1) * (CO * 8) + c0) = rb;
        } else if (c0 < NC) {
            *reinterpret_cast<float4*>(Tb + na * CO + (c0 - CO * 8)) = ra;
            *reinterpret_cast<float4*>(Tb + (na + 1) * CO + (c0 - CO * 8)) = rb;
        }
    }
}

// ---------------- edge NNConv: node-parallel over src-CSR -------------------
// TPN = CO/4 threads per src node; T row (4 outs x 8f + bias) lives in registers.
template<int CO, int TPN>
__global__ void __launch_bounds__(32 * TPN) edge_nnconv_kernel(
        const int* __restrict__ off, const int* __restrict__ sdst,
        const float* __restrict__ sea,
        const float* __restrict__ T, const float* __restrict__ Tb,
        float* __restrict__ agg) {
    int t = threadIdx.x;
    int g = t / TPN;
    int o0 = (t - g * TPN) * 4;
    int n = blockIdx.x * 32 + g;

    int beg = off[n], end = off[n + 1];
    if (beg == end) return;

    const float4* tp = reinterpret_cast<const float4*>(T + (n * CO + o0) * 8);
    float4 T0 = tp[0], T1 = tp[1], T2 = tp[2], T3 = tp[3];
    float4 T4 = tp[4], T5 = tp[5], T6 = tp[6], T7 = tp[7];
    float4 bb = *reinterpret_cast<const float4*>(Tb + n * CO + o0);

    for (int e = beg; e < end; e++) {
        int dst = sdst[e];
        const float4* eap = reinterpret_cast<const float4*>(sea + e * 8);
        float4 a0 = eap[0], a1 = eap[1];
        float r0 = bb.x + a0.x * T0.x + a0.y * T0.y + a0.z * T0.z + a0.w * T0.w
                        + a1.x * T1.x + a1.y * T1.y + a1.z * T1.z + a1.w * T1.w;
        float r1 = bb.y + a0.x * T2.x + a0.y * T2.y + a0.z * T2.z + a0.w * T2.w
                        + a1.x * T3.x + a1.y * T3.y + a1.z * T3.z + a1.w * T3.w;
        float r2 = bb.z + a0.x * T4.x + a0.y * T4.y + a0.z * T4.z + a0.w * T4.w
                        + a1.x * T5.x + a1.y * T5.y + a1.z * T5.z + a1.w * T5.w;
        float r3 = bb.w + a0.x * T6.x + a0.y * T6.y + a0.z * T6.z + a0.w * T6.w
                        + a1.x * T7.x + a1.y * T7.y + a1.z * T7.z + a1.w * T7.w;
        red_add_v4(agg + dst * CO + o0, r0, r1, r2, r3);
    }
}

// ---------------- H = relu(agg + X @ root + bias) ---------------------------
template<int K, int CO>
__global__ void root_relu_kernel(const float* __restrict__ agg, const float* __restrict__ X,
                                 const float* __restrict__ root, const float* __restrict__ bias,
                                 float* __restrict__ H) {
    constexpr int NB = 16;
    constexpr int ITEMS = NB * CO / 256;
    __shared__ float xs[NB][K];
    int n0 = blockIdx.x * NB;
    for (int idx = threadIdx.x; idx < NB * K; idx += 256)
        xs[idx / K][idx % K] = X[n0 * K + idx];
    __syncthreads();
#pragma unroll
    for (int j = 0; j < ITEMS; j++) {
        int item = threadIdx.x + j * 256;
        int nl = item / CO, o = item - nl * CO;
        float acc = agg[(n0 + nl) * CO + o] + bias[o];
#pragma unroll 4
        for (int i = 0; i < K; i++) acc += xs[nl][i] * root[i * CO + o];
        H[(n0 + nl) * CO + o] = fmaxf(acc, 0.f);
    }
}

// ---------------- fused: h2 = relu(...); hm = h2@muw; hl = h2@lsw -----------
__global__ void root2_heads_kernel(const float* __restrict__ agg, const float* __restrict__ H1,
                                   const float* __restrict__ root, const float* __restrict__ bias,
                                   const float* __restrict__ muw, const float* __restrict__ lsw,
                                   float* __restrict__ hm, float* __restrict__ hl) {
    __shared__ float xs[16][48];
    __shared__ float hs[16][32];
    int n0 = blockIdx.x * 16;
    for (int idx = threadIdx.x; idx < 16 * 48; idx += 256)
        xs[idx / 48][idx % 48] = H1[n0 * 48 + idx];
    __syncthreads();
#pragma unroll
    for (int j = 0; j < 2; j++) {
        int item = threadIdx.x + j * 256;
        int nl = item >> 5, o = item & 31;
        float acc = agg[(n0 + nl) * 32 + o] + bias[o];
#pragma unroll 4
        for (int i = 0; i < 48; i++) acc += xs[nl][i] * root[i * 32 + o];
        hs[nl][o] = fmaxf(acc, 0.f);
    }
    __syncthreads();
#pragma unroll
    for (int j = 0; j < 2; j++) {
        int item = threadIdx.x + j * 256;
        int nl = item >> 5;
        int r = item & 31;
        int head = r >> 4, o = r & 15;
        const float* W = head ? lsw : muw;
        float acc = 0.f;
#pragma unroll
        for (int i = 0; i < 32; i++) acc += hs[nl][i] * W[i * 16 + o];
        (head ? hl : hm)[(n0 + nl) * 16 + o] = acc;
    }
}

// ---------------- GCN scatter: node-parallel over src-CSR -------------------
// 8 threads per src node (head x quarter); h rows live in registers.
__global__ void __launch_bounds__(256) gcn_edge_kernel(
        const int* __restrict__ off, const int* __restrict__ sdst,
        const float* __restrict__ hm, const float* __restrict__ hl,
        const float* __restrict__ dinv,
        float* __restrict__ aggm, float* __restrict__ aggl) {
    int t = threadIdx.x;
    int g = t >> 3;
    int r = t & 7;
    int head = r >> 2, q = r & 3;
    int n = blockIdx.x * 32 + g;
    int beg = off[n], end = off[n + 1];
    if (beg == end) return;

    const float* h = head ? hl : hm;
    float* a = head ? aggl : aggm;
    float4 v = *reinterpret_cast<const float4*>(h + n * 16 + q * 4);
    float ds = dinv[n];
    for (int e = beg; e < end; e++) {
        int dst = sdst[e];
        float w = ds * dinv[dst];
        red_add_v4(a + dst * 16 + q * 4, v.x * w, v.y * w, v.z * w, v.w * w);
    }
}

// ---------------- final: out = agg + h*invdeg + bias (mu then ls) -----------
__global__ void out_kernel(const float* __restrict__ aggm, const float* __restrict__ aggl,
                           const float* __restrict__ hm, const float* __restrict__ hl,
                           const float* __restrict__ invdeg, const float* __restrict__ mub,
                           const float* __restrict__ lsb, float* __restrict__ out) {
    int i4 = blockIdx.x * 256 + threadIdx.x;
    int n = i4 >> 2, q = i4 & 3;
    float iv = invdeg[n];
    float4* out4 = reinterpret_cast<float4*>(out);
    float4 am = reinterpret_cast<const float4*>(aggm)[i4];
    float4 vm = reinterpret_cast<const float4*>(hm)[i4];
    float4 bm = reinterpret_cast<const float4*>(mub)[q];
    out4[i4] = make_float4(am.x + vm.x * iv + bm.x, am.y + vm.y * iv + bm.y,
                           am.z + vm.z * iv + bm.z, am.w + vm.w * iv + bm.w);
    float4 al = reinterpret_cast<const float4*>(aggl)[i4];
    float4 vl = reinterpret_cast<const float4*>(hl)[i4];
    float4 bl = reinterpret_cast<const float4*>(lsb)[q];
    out4[32768 + i4] = make_float4(al.x + vl.x * iv + bl.x, al.y + vl.y * iv + bl.y,
                                   al.z + vl.z * iv + bl.z, al.w + vl.w * iv + bl.w);
}

// ---------------- launcher --------------------------------------------------
extern "C" void kernel_launch(void* const* d_in, const int* in_sizes, int n_in,
                              void* d_out, int out_size) {
    const float* x      = (const float*)d_in[0];
    const int*   ei     = (const int*)  d_in[1];
    const float* ea     = (const float*)d_in[2];
    const float* nn1_w  = (const float*)d_in[3];
    const float* nn1_b  = (const float*)d_in[4];
    const float* root1  = (const float*)d_in[5];
    const float* bias1  = (const float*)d_in[6];
    const float* nn2_w  = (const float*)d_in[7];
    const float* nn2_b  = (const float*)d_in[8];
    const float* root2  = (const float*)d_in[9];
    const float* bias2  = (const float*)d_in[10];
    const float* mu_w   = (const float*)d_in[11];
    const float* mu_b   = (const float*)d_in[12];
    const float* ls_w   = (const float*)d_in[13];
    const float* ls_b   = (const float*)d_in[14];
    float* out = (float*)d_out;

    void *pz, *pT1, *pTb1, *pT2, *pTb2, *ph1, *phm, *phl;
    void *pWt1, *pWt2, *pdinv, *pinvdeg, *poff, *pcur, *psdst, *psea;
    cudaGetSymbolAddress(&pz, g_zbuf);
    cudaGetSymbolAddress(&pT1, g_T1);
    cudaGetSymbolAddress(&pTb1, g_Tb1);
    cudaGetSymbolAddress(&pT2, g_T2);
    cudaGetSymbolAddress(&pTb2, g_Tb2);
    cudaGetSymbolAddress(&ph1, g_h1);
    cudaGetSymbolAddress(&phm, g_hm);
    cudaGetSymbolAddress(&phl, g_hl);
    cudaGetSymbolAddress(&pWt1, g_Wt1);
    cudaGetSymbolAddress(&pWt2, g_Wt2);
    cudaGetSymbolAddress(&pdinv, g_dinv);
    cudaGetSymbolAddress(&pinvdeg, g_invdeg);
    cudaGetSymbolAddress(&poff, g_off);
    cudaGetSymbolAddress(&pcur, g_cursor);
    cudaGetSymbolAddress(&psdst, g_sdst);
    cudaGetSymbolAddress(&psea, g_sea);

    float* zb = (float*)pz;
    int*   deg    = (int*)(zb + OFF_DEG);
    int*   outcnt = (int*)(zb + OFF_OUTCNT);
    float* agg1   = zb + OFF_AGG1;
    float* agg2   = zb + OFF_AGG2;
    float* aggm   = zb + OFF_AGGM;
    float* aggl   = zb + OFF_AGGL;

    cudaMemsetAsync(pz, 0, ZFLOATS * sizeof(float), 0);

    prep_kernel<<<418, 256>>>(ei, nn1_w, nn1_b, nn2_w, nn2_b,
                              outcnt, deg, (float*)pWt1, (float*)pWt2);
    scan_dinv_kernel<<<9, 1024>>>(outcnt, deg, (int*)poff, (int*)pcur,
                                  (float*)pdinv, (float*)pinvdeg);
    perm_kernel<<<256, 256>>>(ei, ea, (int*)pcur, (int*)psdst, (float*)psea);

    // layer 1
    node_gemm_kernel<64, 48><<<dim3(4, 128), 256>>>(x, (float*)pWt1, (float*)pT1, (float*)pTb1);
    edge_nnconv_kernel<48, 12><<<NN / 32, 384>>>((int*)poff, (int*)psdst, (float*)psea,
                                                 (float*)pT1, (float*)pTb1, agg1);
    root_relu_kernel<64, 48><<<NN / 16, 256>>>(agg1, x, root1, bias1, (float*)ph1);

    // layer 2
    node_gemm_kernel<48, 32><<<dim3(3, 128), 256>>>((float*)ph1, (float*)pWt2,
                                                    (float*)pT2, (float*)pTb2);
    edge_nnconv_kernel<32, 8><<<NN / 32, 256>>>((int*)poff, (int*)psdst, (float*)psea,
                                                (float*)pT2, (float*)pTb2, agg2);
    root2_heads_kernel<<<NN / 16, 256>>>(agg2, (float*)ph1, root2, bias2,
                                         mu_w, ls_w, (float*)phm, (float*)phl);

    // GCN scatter + output
    gcn_edge_kernel<<<NN / 32, 256>>>((int*)poff, (int*)psdst, (float*)phm, (float*)phl,
                                      (float*)pdinv, aggm, aggl);
    out_kernel<<<128, 256>>>(aggm, aggl, (float*)phm, (float*)phl,
                             (float*)pinvdeg, mu_b, ls_b, out);
}